// round 2
// baseline (speedup 1.0000x reference)
#include <cuda_runtime.h>
#include <cstddef>
#include <math.h>

#define T_ 4
#define B_ 16
#define C_ 256
#define N_ 512
#define H_ 1024

// ---------------- scratch (device globals; no allocation allowed) ----------
__device__ float g_qs[(size_t)T_*B_*C_*N_];
__device__ float g_ks[(size_t)T_*B_*C_*N_];
__device__ float g_vs[(size_t)T_*B_*C_*N_];
__device__ float g_rs[(size_t)T_*B_*C_*N_];
__device__ float g_x1[(size_t)T_*B_*C_*N_];
__device__ float g_h [(size_t)T_*B_*H_*N_];

__device__ __forceinline__ float* buf_ptr(int id){
  switch(id){
    case 0: return g_qs; case 1: return g_ks; case 2: return g_vs;
    case 3: return g_rs; case 4: return g_x1; default: return g_h;
  }
}

// ------------- fused GEMM + (reference-order) BN + LIF scan over T
// pre-act:  acc = sum_c W[o,c] X[t,b,c,n]          (serial ascending k, fp32)
// epilogue: y  = ((acc + bias) - mean) * s + beta  (elementwise, s = g/sqrt(v+eps))
// LIF over t held in registers; optional fused residual add on the spike output.
// Block tile: 128 (o) x 64 (n), 256 threads, 8x4 micro-tile, BK=16.
__global__ __launch_bounds__(256, 2)
void gemm_lif_kernel(const float* __restrict__ Xext, float* __restrict__ outext,
                     const float* __restrict__ resext,
                     int xid, int oid, int rid,
                     const float* __restrict__ W, const float* __restrict__ bn,
                     const float* __restrict__ bias, int Cin, int Cout)
{
  __shared__ float sW[16][128];   // [k][o]
  __shared__ float sX[16][64];    // [k][n]

  const float* X   = (xid >= 0) ? buf_ptr(xid) : Xext;
  float* out       = (oid >= 0) ? buf_ptr(oid) : outext;
  const float* res = (rid == -2) ? nullptr : ((rid >= 0) ? buf_ptr(rid) : resext);

  const int b  = blockIdx.z;
  const int o0 = blockIdx.y * 128;
  const int n0 = blockIdx.x * 64;
  const int tid = threadIdx.x;
  const int to = tid >> 4;          // 0..15 -> o micro row (8 each)
  const int tn = tid & 15;          // 0..15 -> n micro col (4 each)

  const int lwo = tid >> 1;         // 0..127
  const int lwk = (tid & 1) * 8;    // 0 or 8
  const int lxk = tid >> 4;         // 0..15
  const int lxn = (tid & 15) * 4;   // 0..60

  // per-channel BN params (reference order: s = gamma / sqrt(var + eps))
  float s_r[8], m_r[8], be_r[8], bc_r[8];
#pragma unroll
  for (int i = 0; i < 8; i++) {
    const int o = o0 + to*8 + i;
    const float g  = bn[o];
    const float be = bn[Cout + o];
    const float mm = bn[2*Cout + o];
    const float vv = bn[3*Cout + o];
    s_r[i]  = g / sqrtf(vv + 1e-5f);
    m_r[i]  = mm;
    be_r[i] = be;
    bc_r[i] = bias ? bias[o] : 0.0f;
  }

  float mem[8][4];
#pragma unroll
  for (int i=0;i<8;i++)
#pragma unroll
    for (int j=0;j<4;j++) mem[i][j] = 0.0f;

  for (int t = 0; t < T_; t++) {
    float acc[8][4];
#pragma unroll
    for (int i=0;i<8;i++)
#pragma unroll
      for (int j=0;j<4;j++) acc[i][j] = 0.0f;

    const float* Xtb = X + (size_t)(t*B_ + b) * Cin * N_;

    for (int kk = 0; kk < Cin; kk += 16) {
      __syncthreads();
      {
        const float* wp = W + (size_t)(o0 + lwo) * Cin + kk + lwk;
        float4 w0 = *(const float4*)(wp);
        float4 w1 = *(const float4*)(wp + 4);
        sW[lwk+0][lwo] = w0.x; sW[lwk+1][lwo] = w0.y;
        sW[lwk+2][lwo] = w0.z; sW[lwk+3][lwo] = w0.w;
        sW[lwk+4][lwo] = w1.x; sW[lwk+5][lwo] = w1.y;
        sW[lwk+6][lwo] = w1.z; sW[lwk+7][lwo] = w1.w;
      }
      *(float4*)&sX[lxk][lxn] = *(const float4*)(Xtb + (size_t)(kk + lxk) * N_ + n0 + lxn);
      __syncthreads();
#pragma unroll
      for (int k = 0; k < 16; k++) {
        float4 a0 = *(const float4*)&sW[k][to*8];
        float4 a1 = *(const float4*)&sW[k][to*8 + 4];
        float4 b4 = *(const float4*)&sX[k][tn*4];
        float a[8] = {a0.x,a0.y,a0.z,a0.w,a1.x,a1.y,a1.z,a1.w};
        float bb[4] = {b4.x,b4.y,b4.z,b4.w};
#pragma unroll
        for (int i=0;i<8;i++)
#pragma unroll
          for (int j=0;j<4;j++) acc[i][j] = fmaf(a[i], bb[j], acc[i][j]);
      }
    }

    // epilogue: bias -> BN (reference order) -> LIF -> optional residual
#pragma unroll
    for (int i=0;i<8;i++) {
      const int o = o0 + to*8 + i;
      const size_t row = ((size_t)(t*B_ + b) * Cout + o) * N_ + n0 + tn*4;
      float v[4];
#pragma unroll
      for (int j=0;j<4;j++) {
        float ypre = acc[i][j] + bc_r[i];                 // conv bias (0 if none)
        float y    = fmaf(ypre - m_r[i], s_r[i], be_r[i]); // (y-m)*s + beta
        float m2 = mem[i][j] + (y - mem[i][j]) * 0.5f;     // mem + (y-mem)/TAU
        bool fire = (m2 > 0.5f);                           // spike(mem - 0.5)
        mem[i][j] = fire ? 0.0f : m2;                      // hard reset
        v[j] = fire ? 1.0f : 0.0f;
      }
      if (res) {
        float4 rr = *(const float4*)(res + row);
        v[0] += rr.x; v[1] += rr.y; v[2] += rr.z; v[3] += rr.w;
      }
      float4 o4; o4.x=v[0]; o4.y=v[1]; o4.z=v[2]; o4.w=v[3];
      *(float4*)(out + row) = o4;
    }
  }
}

// ------------- spiking linear attention + attn-LIF (bit-exact integer math)
// r[t,b,h*16+d,n] = 0.0625 * sum_d1 q[.,d1,n] * KV[d1][d],
// KV[d1][d2] = sum_m k[.,d1,m] * v[.,d2,m]   (binary spikes -> exact ints)
__global__ __launch_bounds__(256)
void attn_lif_kernel()
{
  __shared__ float sV[16][521];   // padded: conflict-free column reads
  __shared__ float sKV[16][17];
  const int b = blockIdx.x;
  const int h = blockIdx.y;
  const int tid = threadIdx.x;
  const int d1 = tid >> 4, d2 = tid & 15;
  const int lr = tid >> 4;          // v-row for staging
  const int lm = (tid & 15) * 32;   // m start for staging

  float mem[2][16];
#pragma unroll
  for (int j=0;j<2;j++)
#pragma unroll
    for (int d=0; d<16; d++) mem[j][d] = 0.0f;

  for (int t=0; t<T_; t++){
    const size_t base = ((size_t)(t*B_ + b) * C_ + h*16) * N_;
    __syncthreads();   // prior iteration done reading sV/sKV
    {
      const float* vr = g_vs + base + (size_t)lr * N_ + lm;
#pragma unroll
      for (int u=0; u<8; u++){
        float4 v4 = *(const float4*)(vr + u*4);
        sV[lr][lm + u*4 + 0] = v4.x;
        sV[lr][lm + u*4 + 1] = v4.y;
        sV[lr][lm + u*4 + 2] = v4.z;
        sV[lr][lm + u*4 + 3] = v4.w;
      }
    }
    __syncthreads();
    {
      const float* kr = g_ks + base + (size_t)d1 * N_;
      float kv = 0.0f;
#pragma unroll 8
      for (int m=0; m<N_; m++) kv = fmaf(__ldg(kr + m), sV[d2][m], kv);
      sKV[d1][d2] = kv;
    }
    __syncthreads();
#pragma unroll
    for (int half=0; half<2; half++){
      const int n = tid + half*256;
      float qv[16];
#pragma unroll
      for (int dd=0; dd<16; dd++) qv[dd] = g_qs[base + (size_t)dd*N_ + n];
#pragma unroll
      for (int d=0; d<16; d++){
        float r = 0.0f;
#pragma unroll
        for (int dd=0; dd<16; dd++) r = fmaf(qv[dd], sKV[dd][d], r);
        r *= 0.0625f;   // SCALE * SCALE (exact: dyadic integers)
        float m2 = mem[half][d] + (r - mem[half][d]) * 0.5f;
        bool fire = (m2 > 0.5f);
        mem[half][d] = fire ? 0.0f : m2;
        g_rs[base + (size_t)d*N_ + n] = fire ? 1.0f : 0.0f;
      }
    }
  }
}

// --------------------------------------------------------------------------
extern "C" void kernel_launch(void* const* d_in, const int* in_sizes, int n_in,
                              void* d_out, int out_size)
{
  const float* x       = (const float*)d_in[0];
  const float* q_w     = (const float*)d_in[1];
  const float* q_bn    = (const float*)d_in[2];
  const float* k_w     = (const float*)d_in[3];
  const float* k_bn    = (const float*)d_in[4];
  const float* v_w     = (const float*)d_in[5];
  const float* v_bn    = (const float*)d_in[6];
  const float* proj_w  = (const float*)d_in[7];
  const float* proj_bn = (const float*)d_in[8];
  const float* fc1_w   = (const float*)d_in[9];
  const float* fc1_b   = (const float*)d_in[10];
  const float* fc1_bn  = (const float*)d_in[11];
  const float* fc2_w   = (const float*)d_in[12];
  const float* fc2_b   = (const float*)d_in[13];
  const float* fc2_bn  = (const float*)d_in[14];
  float* out = (float*)d_out;

  dim3 blk(256);
  dim3 gconv(N_/64, C_/128, B_);     // (8,2,16)

  // q, k, v = conv+bn+lif(x) -> binary spikes
  gemm_lif_kernel<<<gconv, blk>>>(x, nullptr, nullptr, -1, 0, -2, q_w, q_bn, nullptr, C_, C_);
  gemm_lif_kernel<<<gconv, blk>>>(x, nullptr, nullptr, -1, 1, -2, k_w, k_bn, nullptr, C_, C_);
  gemm_lif_kernel<<<gconv, blk>>>(x, nullptr, nullptr, -1, 2, -2, v_w, v_bn, nullptr, C_, C_);

  // linear attention (q (kT v)) * 0.0625 + attn-LIF -> g_rs
  attn_lif_kernel<<<dim3(B_, 16), blk>>>();

  // proj conv+bn+lif, fused residual: x1 = x + spike
  gemm_lif_kernel<<<gconv, blk>>>(nullptr, nullptr, x, 3, 4, -1, proj_w, proj_bn, nullptr, C_, C_);

  // fc1 conv+bn+lif -> g_h (Cout=1024)
  dim3 gfc1(N_/64, H_/128, B_);      // (8,8,16)
  gemm_lif_kernel<<<gfc1, blk>>>(nullptr, nullptr, nullptr, 4, 5, -2, fc1_w, fc1_bn, fc1_b, C_, H_);

  // fc2 conv+bn+lif, fused residual: out = x1 + spike (Cin=1024)
  gemm_lif_kernel<<<gconv, blk>>>(nullptr, out, nullptr, 5, -1, 4, fc2_w, fc2_bn, fc2_b, H_, C_);
}

// round 3
// speedup vs baseline: 1.2559x; 1.2559x over previous
#include <cuda_runtime.h>
#include <cstddef>
#include <math.h>

#define T_ 4
#define B_ 16
#define C_ 256
#define N_ 512
#define H_ 1024

// ---------------- scratch (device globals; no allocation allowed) ----------
__device__ float g_qs[(size_t)T_*B_*C_*N_];
__device__ float g_ks[(size_t)T_*B_*C_*N_];
__device__ float g_vs[(size_t)T_*B_*C_*N_];
__device__ float g_rs[(size_t)T_*B_*C_*N_];
__device__ float g_x1[(size_t)T_*B_*C_*N_];
__device__ float g_h [(size_t)T_*B_*H_*N_];

__device__ __forceinline__ float* buf_ptr(int id){
  switch(id){
    case 0: return g_qs; case 1: return g_ks; case 2: return g_vs;
    case 3: return g_rs; case 4: return g_x1; default: return g_h;
  }
}

// ---------------- packed f32x2 helpers (bit-exact per-lane IEEE fma) -------
__device__ __forceinline__ unsigned long long pk2(float v){
  unsigned long long r; unsigned u = __float_as_uint(v);
  asm("mov.b64 %0, {%1, %1};" : "=l"(r) : "r"(u));
  return r;
}
__device__ __forceinline__ void fma2(unsigned long long &d,
                                     unsigned long long a, unsigned long long b){
  asm("fma.rn.f32x2 %0, %1, %2, %0;" : "+l"(d) : "l"(a), "l"(b));
}
__device__ __forceinline__ float2 unpk(unsigned long long p){
  unsigned lo, hi;
  asm("mov.b64 {%0, %1}, %2;" : "=r"(lo), "=r"(hi) : "l"(p));
  return make_float2(__uint_as_float(lo), __uint_as_float(hi));
}

// ------------- fused GEMM + (reference-order) BN + LIF scan over T
// pre-act:  acc = sum_c W[o,c] X[t,b,c,n]   (serial ascending k, fp32 fma —
//           FFMA2 pairs ADJACENT O-ROWS, never splits a sum: bit-exact)
// epilogue: y = ((acc + bias) - mean) * s + beta ; LIF over t in registers.
// Block tile: 128 (o) x 64 (n), 256 threads, 8x4 micro-tile, BK=16.
__device__ __forceinline__ void gemm_lif_body(
    const float* __restrict__ X, float* __restrict__ out,
    const float* __restrict__ res,
    const float* __restrict__ W, const float* __restrict__ bn,
    const float* __restrict__ bias, int Cin, int Cout,
    int b, int o0, int n0)
{
  __shared__ __align__(16) float sW[16][128];   // [k][o]
  __shared__ __align__(16) float sX[16][64];    // [k][n]

  const int tid = threadIdx.x;
  const int to = tid >> 4;          // 0..15 -> o micro row (8 each)
  const int tn = tid & 15;          // 0..15 -> n micro col (4 each)

  const int lwo = tid >> 1;         // 0..127
  const int lwk = (tid & 1) * 8;    // 0 or 8
  const int lxk = tid >> 4;         // 0..15
  const int lxn = (tid & 15) * 4;   // 0..60

  // per-channel BN params (reference order: s = gamma / sqrt(var + eps))
  float s_r[8], m_r[8], be_r[8], bc_r[8];
#pragma unroll
  for (int i = 0; i < 8; i++) {
    const int o = o0 + to*8 + i;
    const float g  = bn[o];
    const float be = bn[Cout + o];
    const float mm = bn[2*Cout + o];
    const float vv = bn[3*Cout + o];
    s_r[i]  = g / sqrtf(vv + 1e-5f);
    m_r[i]  = mm;
    be_r[i] = be;
    bc_r[i] = bias ? bias[o] : 0.0f;
  }

  float mem[8][4];
#pragma unroll
  for (int i=0;i<8;i++)
#pragma unroll
    for (int j=0;j<4;j++) mem[i][j] = 0.0f;

#pragma unroll 1
  for (int t = 0; t < T_; t++) {
    // accp[ip][j] packs outputs (o = to*8 + 2*ip, 2*ip+1) for n = tn*4 + j
    unsigned long long accp[4][4];
#pragma unroll
    for (int i=0;i<4;i++)
#pragma unroll
      for (int j=0;j<4;j++) accp[i][j] = 0ULL;

    const float* Xtb = X + (size_t)(t*B_ + b) * Cin * N_;

#pragma unroll 1
    for (int kk = 0; kk < Cin; kk += 16) {
      __syncthreads();
      {
        const float* wp = W + (size_t)(o0 + lwo) * Cin + kk + lwk;
        float4 w0 = *(const float4*)(wp);
        float4 w1 = *(const float4*)(wp + 4);
        sW[lwk+0][lwo] = w0.x; sW[lwk+1][lwo] = w0.y;
        sW[lwk+2][lwo] = w0.z; sW[lwk+3][lwo] = w0.w;
        sW[lwk+4][lwo] = w1.x; sW[lwk+5][lwo] = w1.y;
        sW[lwk+6][lwo] = w1.z; sW[lwk+7][lwo] = w1.w;
      }
      *(float4*)&sX[lxk][lxn] = *(const float4*)(Xtb + (size_t)(kk + lxk) * N_ + n0 + lxn);
      __syncthreads();
#pragma unroll
      for (int k = 0; k < 16; k++) {
        ulonglong2 au0 = *(const ulonglong2*)&sW[k][to*8];     // (o0,o1),(o2,o3)
        ulonglong2 au1 = *(const ulonglong2*)&sW[k][to*8 + 4]; // (o4,o5),(o6,o7)
        float4 bf = *(const float4*)&sX[k][tn*4];
        unsigned long long pb0 = pk2(bf.x), pb1 = pk2(bf.y),
                           pb2 = pk2(bf.z), pb3 = pk2(bf.w);
        unsigned long long ap[4] = {au0.x, au0.y, au1.x, au1.y};
#pragma unroll
        for (int ip=0; ip<4; ip++){
          fma2(accp[ip][0], ap[ip], pb0);
          fma2(accp[ip][1], ap[ip], pb1);
          fma2(accp[ip][2], ap[ip], pb2);
          fma2(accp[ip][3], ap[ip], pb3);
        }
      }
    }

    // epilogue: bias -> BN (reference order) -> LIF -> optional residual
#pragma unroll
    for (int ip=0; ip<4; ip++) {
      float2 p0 = unpk(accp[ip][0]), p1 = unpk(accp[ip][1]),
             p2 = unpk(accp[ip][2]), p3 = unpk(accp[ip][3]);
      float accs[2][4] = {{p0.x,p1.x,p2.x,p3.x},{p0.y,p1.y,p2.y,p3.y}};
#pragma unroll
      for (int h2=0; h2<2; h2++) {
        const int i = 2*ip + h2;
        const int o = o0 + to*8 + i;
        const size_t row = ((size_t)(t*B_ + b) * Cout + o) * N_ + n0 + tn*4;
        float v[4];
#pragma unroll
        for (int j=0;j<4;j++) {
          float ypre = accs[h2][j] + bc_r[i];                  // conv bias (0 if none)
          float y    = fmaf(ypre - m_r[i], s_r[i], be_r[i]);   // (y-m)*s + beta
          float m2 = mem[i][j] + (y - mem[i][j]) * 0.5f;       // mem + (y-mem)/TAU
          bool fire = (m2 > 0.5f);                             // spike(mem - 0.5)
          mem[i][j] = fire ? 0.0f : m2;                        // hard reset
          v[j] = fire ? 1.0f : 0.0f;
        }
        if (res) {
          float4 rr = *(const float4*)(res + row);
          v[0] += rr.x; v[1] += rr.y; v[2] += rr.z; v[3] += rr.w;
        }
        float4 o4; o4.x=v[0]; o4.y=v[1]; o4.z=v[2]; o4.w=v[3];
        *(float4*)(out + row) = o4;
      }
    }
  }
}

// q,k,v fused into one launch: blockIdx.y in [0,6): gemm = gy>>1, o0 = (gy&1)*128
__global__ __launch_bounds__(256, 2)
void qkv_gemm_kernel(const float* __restrict__ x,
                     const float* __restrict__ Wq, const float* __restrict__ bnq,
                     const float* __restrict__ Wk, const float* __restrict__ bnk,
                     const float* __restrict__ Wv, const float* __restrict__ bnv)
{
  const int gy = blockIdx.y;
  const int gemm = gy >> 1;
  const int o0 = (gy & 1) * 128;
  const float* W  = (gemm == 0) ? Wq  : (gemm == 1) ? Wk  : Wv;
  const float* bn = (gemm == 0) ? bnq : (gemm == 1) ? bnk : bnv;
  float* out = buf_ptr(gemm);
  gemm_lif_body(x, out, nullptr, W, bn, nullptr, C_, C_,
                blockIdx.z, o0, blockIdx.x * 64);
}

__global__ __launch_bounds__(256, 2)
void gemm_lif_kernel(const float* __restrict__ Xext, float* __restrict__ outext,
                     const float* __restrict__ resext,
                     int xid, int oid, int rid,
                     const float* __restrict__ W, const float* __restrict__ bn,
                     const float* __restrict__ bias, int Cin, int Cout)
{
  const float* X   = (xid >= 0) ? buf_ptr(xid) : Xext;
  float* out       = (oid >= 0) ? buf_ptr(oid) : outext;
  const float* res = (rid == -2) ? nullptr : ((rid >= 0) ? buf_ptr(rid) : resext);
  gemm_lif_body(X, out, res, W, bn, bias, Cin, Cout,
                blockIdx.z, blockIdx.y * 128, blockIdx.x * 64);
}

// ------------- spiking linear attention + attn-LIF (bit-exact integer math)
// KV[d1][d2] = sum_m k[d1,m] * v[d2,m]  -> bitpack + popc (spikes binary)
// r[t,b,h*16+d,n] = 0.0625 * sum_d1 q[.,d1,n] * KV[d1][d] ; LIF over t.
__global__ __launch_bounds__(256)
void attn_lif_kernel()
{
  __shared__ unsigned kb[16][17], vb[16][17];
  __shared__ float sKV[16][17];
  const int b = blockIdx.x;
  const int h = blockIdx.y;
  const int tid = threadIdx.x;
  const int warp = tid >> 5, lane = tid & 31;
  const int d1 = tid >> 4, d2 = tid & 15;

  float mem[2][16];
#pragma unroll
  for (int j=0;j<2;j++)
#pragma unroll
    for (int d=0; d<16; d++) mem[j][d] = 0.0f;

#pragma unroll 1
  for (int t=0; t<T_; t++){
    const size_t base = ((size_t)(t*B_ + b) * C_ + h*16) * N_;
    __syncthreads();   // prior iteration done reading kb/vb/sKV

    // bitpack k,v: each warp handles 32 (row,word) pairs via ballot
#pragma unroll 4
    for (int i = 0; i < 32; i++){
      const int idx = warp * 32 + i;          // 0..255
      const int row = idx >> 4, word = idx & 15;
      const size_t off = base + (size_t)row * N_ + word * 32 + lane;
      unsigned uk = __ballot_sync(0xffffffffu, g_ks[off] != 0.0f);
      unsigned uv = __ballot_sync(0xffffffffu, g_vs[off] != 0.0f);
      if (lane == 0){ kb[row][word] = uk; vb[row][word] = uv; }
    }
    __syncthreads();

    // KV via popc (exact integers)
    {
      int kv = 0;
#pragma unroll
      for (int w=0; w<16; w++) kv += __popc(kb[d1][w] & vb[d2][w]);
      sKV[d1][d2] = (float)kv;
    }
    __syncthreads();

    // r = q @ KV, scaled, then attn-LIF (all dyadic-exact)
#pragma unroll
    for (int half=0; half<2; half++){
      const int n = tid + half*256;
      float qv[16];
#pragma unroll
      for (int dd=0; dd<16; dd++) qv[dd] = g_qs[base + (size_t)dd*N_ + n];
#pragma unroll
      for (int d=0; d<16; d++){
        float r = 0.0f;
#pragma unroll
        for (int dd=0; dd<16; dd++) r = fmaf(qv[dd], sKV[dd][d], r);
        r *= 0.0625f;   // SCALE * SCALE (exact)
        float m2 = mem[half][d] + (r - mem[half][d]) * 0.5f;
        bool fire = (m2 > 0.5f);
        mem[half][d] = fire ? 0.0f : m2;
        g_rs[base + (size_t)d*N_ + n] = fire ? 1.0f : 0.0f;
      }
    }
  }
}

// --------------------------------------------------------------------------
extern "C" void kernel_launch(void* const* d_in, const int* in_sizes, int n_in,
                              void* d_out, int out_size)
{
  const float* x       = (const float*)d_in[0];
  const float* q_w     = (const float*)d_in[1];
  const float* q_bn    = (const float*)d_in[2];
  const float* k_w     = (const float*)d_in[3];
  const float* k_bn    = (const float*)d_in[4];
  const float* v_w     = (const float*)d_in[5];
  const float* v_bn    = (const float*)d_in[6];
  const float* proj_w  = (const float*)d_in[7];
  const float* proj_bn = (const float*)d_in[8];
  const float* fc1_w   = (const float*)d_in[9];
  const float* fc1_b   = (const float*)d_in[10];
  const float* fc1_bn  = (const float*)d_in[11];
  const float* fc2_w   = (const float*)d_in[12];
  const float* fc2_b   = (const float*)d_in[13];
  const float* fc2_bn  = (const float*)d_in[14];
  float* out = (float*)d_out;

  dim3 blk(256);

  // q, k, v = conv+bn+lif(x) -> binary spikes (one fused launch)
  qkv_gemm_kernel<<<dim3(N_/64, 6, B_), blk>>>(x, q_w, q_bn, k_w, k_bn, v_w, v_bn);

  // linear attention (q (kT v)) * 0.0625 + attn-LIF -> g_rs
  attn_lif_kernel<<<dim3(B_, 16), blk>>>();

  // proj conv+bn+lif, fused residual: x1 = x + spike
  gemm_lif_kernel<<<dim3(N_/64, C_/128, B_), blk>>>(nullptr, nullptr, x, 3, 4, -1,
                                                    proj_w, proj_bn, nullptr, C_, C_);

  // fc1 conv+bn+lif -> g_h (Cout=1024)
  gemm_lif_kernel<<<dim3(N_/64, H_/128, B_), blk>>>(nullptr, nullptr, nullptr, 4, 5, -2,
                                                    fc1_w, fc1_bn, fc1_b, C_, H_);

  // fc2 conv+bn+lif, fused residual: out = x1 + spike (Cin=1024)
  gemm_lif_kernel<<<dim3(N_/64, C_/128, B_), blk>>>(nullptr, out, nullptr, 5, -1, 4,
                                                    fc2_w, fc2_bn, fc2_b, H_, C_);
}